// round 4
// baseline (speedup 1.0000x reference)
#include <cuda_runtime.h>
#include <cuda_bf16.h>
#include <cstdint>

// ---------------- problem constants ----------------
#define BB 2
#define TT 2048
#define DD 1024
#define NH 16
#define HDIM 64
#define WIN 10
#define MM (BB*TT)          // 4096 rows

// ---------------- scratch (static device, allocation-free) ----------------
__device__ float g_h[(size_t)MM * DD];        // LN output (reused)
__device__ float g_qkv[(size_t)MM * 3 * DD];  // qkv
__device__ float g_o[(size_t)MM * DD];        // attention output
__device__ float g_x1[(size_t)MM * DD];       // x + attn_out
__device__ float g_ff[(size_t)MM * 4 * DD];   // FFN hidden

// ---------------- LayerNorm ----------------
__global__ void ln_kernel(const float* __restrict__ x, const float* __restrict__ g,
                          const float* __restrict__ b, float* __restrict__ out) {
    int row = blockIdx.x;
    const float* xp = x + (size_t)row * DD;
    int t = threadIdx.x; // 256 threads, 4 elements each
    float4 v = *(const float4*)(xp + t * 4);
    float s  = v.x + v.y + v.z + v.w;
    float ss = v.x*v.x + v.y*v.y + v.z*v.z + v.w*v.w;
    __shared__ float rs[8], rss[8];
    #pragma unroll
    for (int off = 16; off; off >>= 1) {
        s  += __shfl_xor_sync(0xffffffffu, s,  off);
        ss += __shfl_xor_sync(0xffffffffu, ss, off);
    }
    if ((t & 31) == 0) { rs[t >> 5] = s; rss[t >> 5] = ss; }
    __syncthreads();
    __shared__ float mean_sh, rstd_sh;
    if (t == 0) {
        float S = 0.f, SS = 0.f;
        #pragma unroll
        for (int i = 0; i < 8; i++) { S += rs[i]; SS += rss[i]; }
        float mean = S * (1.0f / DD);
        float var  = SS * (1.0f / DD) - mean * mean;
        mean_sh = mean;
        rstd_sh = rsqrtf(var + 1e-5f);
    }
    __syncthreads();
    float mean = mean_sh, rstd = rstd_sh;
    float4 gv = *(const float4*)(g + t * 4);
    float4 bv = *(const float4*)(b + t * 4);
    float4 ov;
    ov.x = (v.x - mean) * rstd * gv.x + bv.x;
    ov.y = (v.y - mean) * rstd * gv.y + bv.y;
    ov.z = (v.z - mean) * rstd * gv.z + bv.z;
    ov.w = (v.w - mean) * rstd * gv.w + bv.w;
    *(float4*)(out + (size_t)row * DD + t * 4) = ov;
}

// ---------------- GEMM: C[M,N] = A[M,K] @ W[N,K]^T + bias (+epilogue) ----------------
// Double-buffered smem, global->register prefetch, one barrier per k-iter.
// EPI: 0 = none, 1 = += R (residual), 2 = exact GELU
template<int EPI>
__global__ void __launch_bounds__(256)
gemm_kernel(const float* __restrict__ A, const float* __restrict__ W,
            const float* __restrict__ bias, const float* __restrict__ R,
            float* __restrict__ C, int M, int N, int K) {
    constexpr int BM = 128, BN = 128, BK = 16;
    __shared__ float As[2][BK][BM];
    __shared__ float Bs[2][BK][BN];
    int tid = threadIdx.x;                 // 256
    int tx = tid & 15, ty = tid >> 4;      // 16x16 thread grid, 8x8 micro-tile
    int bm = blockIdx.y * BM, bn = blockIdx.x * BN;

    // each thread stages 2 float4 of A and 2 of B per tile
    int r0 = tid >> 2, c40 = (tid & 3) * 4;               // pos = tid
    int r1 = (256 + tid) >> 2, c41 = ((256 + tid) & 3) * 4; // pos = 256+tid

    float acc[8][8];
    #pragma unroll
    for (int i = 0; i < 8; i++)
        #pragma unroll
        for (int j = 0; j < 8; j++) acc[i][j] = 0.f;

    // prologue: load tile 0 into buffer 0
    float4 a0 = *(const float4*)&A[(size_t)(bm + r0) * K + c40];
    float4 a1 = *(const float4*)&A[(size_t)(bm + r1) * K + c41];
    float4 b0 = *(const float4*)&W[(size_t)(bn + r0) * K + c40];
    float4 b1 = *(const float4*)&W[(size_t)(bn + r1) * K + c41];
    As[0][c40 + 0][r0] = a0.x; As[0][c40 + 1][r0] = a0.y; As[0][c40 + 2][r0] = a0.z; As[0][c40 + 3][r0] = a0.w;
    As[0][c41 + 0][r1] = a1.x; As[0][c41 + 1][r1] = a1.y; As[0][c41 + 2][r1] = a1.z; As[0][c41 + 3][r1] = a1.w;
    Bs[0][c40 + 0][r0] = b0.x; Bs[0][c40 + 1][r0] = b0.y; Bs[0][c40 + 2][r0] = b0.z; Bs[0][c40 + 3][r0] = b0.w;
    Bs[0][c41 + 0][r1] = b1.x; Bs[0][c41 + 1][r1] = b1.y; Bs[0][c41 + 2][r1] = b1.z; Bs[0][c41 + 3][r1] = b1.w;
    __syncthreads();

    int nk = K / BK;
    int cur = 0;
    for (int kt = 0; kt < nk; kt++) {
        // prefetch next tile into registers (overlaps with FMA block below)
        bool has_next = (kt + 1) < nk;
        if (has_next) {
            int k0 = (kt + 1) * BK;
            a0 = *(const float4*)&A[(size_t)(bm + r0) * K + k0 + c40];
            a1 = *(const float4*)&A[(size_t)(bm + r1) * K + k0 + c41];
            b0 = *(const float4*)&W[(size_t)(bn + r0) * K + k0 + c40];
            b1 = *(const float4*)&W[(size_t)(bn + r1) * K + k0 + c41];
        }
        // compute from current buffer
        #pragma unroll
        for (int k = 0; k < BK; k++) {
            float a[8], b[8];
            *(float4*)&a[0] = *(const float4*)&As[cur][k][ty * 8];
            *(float4*)&a[4] = *(const float4*)&As[cur][k][ty * 8 + 4];
            *(float4*)&b[0] = *(const float4*)&Bs[cur][k][tx * 8];
            *(float4*)&b[4] = *(const float4*)&Bs[cur][k][tx * 8 + 4];
            #pragma unroll
            for (int i = 0; i < 8; i++)
                #pragma unroll
                for (int j = 0; j < 8; j++)
                    acc[i][j] += a[i] * b[j];
        }
        // store prefetched tile into the other buffer, single barrier
        if (has_next) {
            int nxt = cur ^ 1;
            As[nxt][c40 + 0][r0] = a0.x; As[nxt][c40 + 1][r0] = a0.y; As[nxt][c40 + 2][r0] = a0.z; As[nxt][c40 + 3][r0] = a0.w;
            As[nxt][c41 + 0][r1] = a1.x; As[nxt][c41 + 1][r1] = a1.y; As[nxt][c41 + 2][r1] = a1.z; As[nxt][c41 + 3][r1] = a1.w;
            Bs[nxt][c40 + 0][r0] = b0.x; Bs[nxt][c40 + 1][r0] = b0.y; Bs[nxt][c40 + 2][r0] = b0.z; Bs[nxt][c40 + 3][r0] = b0.w;
            Bs[nxt][c41 + 0][r1] = b1.x; Bs[nxt][c41 + 1][r1] = b1.y; Bs[nxt][c41 + 2][r1] = b1.z; Bs[nxt][c41 + 3][r1] = b1.w;
            __syncthreads();
            cur = nxt;
        }
    }

    // epilogue
    #pragma unroll
    for (int i = 0; i < 8; i++) {
        int row = bm + ty * 8 + i;
        #pragma unroll
        for (int j = 0; j < 8; j++) {
            int col = bn + tx * 8 + j;
            float v = acc[i][j] + bias[col];
            if (EPI == 1) v += R[(size_t)row * N + col];
            if (EPI == 2) v = 0.5f * v * (1.0f + erff(v * 0.70710678118654752f));
            C[(size_t)row * N + col] = v;
        }
    }
}

// ---------------- banded-causal flash attention ----------------
// grid: (T/64 query tiles, B*H). block: 64 threads, one query row each.
__global__ void __launch_bounds__(64)
attn_kernel(const float* __restrict__ qkv, float* __restrict__ o_out) {
    __shared__ float Ks[64][HDIM];
    __shared__ float Vs[64][HDIM];
    __shared__ float Ss[64][65];
    int bh = blockIdx.y;
    int b = bh / NH, h = bh % NH;
    int q0 = blockIdx.x * 64;
    int t = threadIdx.x;          // 0..63
    int qi = q0 + t;
    const int rowstride = 3 * DD;
    const float* qptr = qkv + ((size_t)(b * TT + qi)) * rowstride + h * HDIM;
    float q[HDIM], o[HDIM];
    #pragma unroll
    for (int d = 0; d < HDIM; d += 4) {
        float4 v4 = *(const float4*)(qptr + d);
        q[d] = v4.x; q[d+1] = v4.y; q[d+2] = v4.z; q[d+3] = v4.w;
    }
    #pragma unroll
    for (int d = 0; d < HDIM; d++) o[d] = 0.f;
    float m = -1e30f, l = 0.f;
    const float scale = 0.125f;   // 1/sqrt(64)

    int kmax = q0 + 63 + WIN;
    if (kmax > TT - 1) kmax = TT - 1;
    int nkt = kmax / 64 + 1;

    for (int kt = 0; kt < nkt; kt++) {
        int kbase = kt * 64;
        // stage K,V (thread t loads key row kbase+t)
        {
            int kj = kbase + t;
            if (kj < TT) {
                const float* kptr = qkv + ((size_t)(b * TT + kj)) * rowstride + DD + h * HDIM;
                const float* vptr = kptr + DD;
                #pragma unroll
                for (int d = 0; d < HDIM; d += 4) {
                    *(float4*)&Ks[t][d] = *(const float4*)(kptr + d);
                    *(float4*)&Vs[t][d] = *(const float4*)(vptr + d);
                }
            } else {
                #pragma unroll
                for (int d = 0; d < HDIM; d += 4) {
                    *(float4*)&Ks[t][d] = make_float4(0.f, 0.f, 0.f, 0.f);
                    *(float4*)&Vs[t][d] = make_float4(0.f, 0.f, 0.f, 0.f);
                }
            }
        }
        __syncthreads();

        int jmax = qi + WIN - kbase;         // band limit
        if (jmax > 63) jmax = 63;
        int jT = TT - 1 - kbase;             // sequence limit
        if (jmax > jT) jmax = jT;

        if (jmax >= 0) {
            float tmax = -1e30f;
            for (int j = 0; j <= jmax; j++) {
                float s = 0.f;
                #pragma unroll
                for (int d = 0; d < HDIM; d++) s += q[d] * Ks[j][d];
                s *= scale;
                Ss[t][j] = s;
                tmax = fmaxf(tmax, s);
            }
            float mnew = fmaxf(m, tmax);
            float corr = __expf(m - mnew);
            l *= corr;
            #pragma unroll
            for (int d = 0; d < HDIM; d++) o[d] *= corr;
            for (int j = 0; j <= jmax; j++) {
                float p = __expf(Ss[t][j] - mnew);
                l += p;
                #pragma unroll
                for (int d = 0; d < HDIM; d++) o[d] += p * Vs[j][d];
            }
            m = mnew;
        }
        __syncthreads();
    }
    float inv = 1.0f / l;
    float* optr = o_out + ((size_t)(b * TT + qi)) * DD + h * HDIM;
    #pragma unroll
    for (int d = 0; d < HDIM; d += 4) {
        float4 v4 = make_float4(o[d] * inv, o[d+1] * inv, o[d+2] * inv, o[d+3] * inv);
        *(float4*)(optr + d) = v4;
    }
}

// ---------------- launch ----------------
extern "C" void kernel_launch(void* const* d_in, const int* in_sizes, int n_in,
                              void* d_out, int out_size) {
    const float* x         = (const float*)d_in[0];
    const float* in_proj_w = (const float*)d_in[1];
    const float* in_proj_b = (const float*)d_in[2];
    const float* out_w     = (const float*)d_in[3];
    const float* out_b     = (const float*)d_in[4];
    const float* ln1_g     = (const float*)d_in[5];
    const float* ln1_b     = (const float*)d_in[6];
    const float* w1        = (const float*)d_in[7];
    const float* b1        = (const float*)d_in[8];
    const float* w2        = (const float*)d_in[9];
    const float* b2        = (const float*)d_in[10];
    const float* ln2_g     = (const float*)d_in[11];
    const float* ln2_b     = (const float*)d_in[12];
    float* out = (float*)d_out;

    float *h_p, *qkv_p, *o_p, *x1_p, *ff_p;
    cudaGetSymbolAddress((void**)&h_p,   g_h);
    cudaGetSymbolAddress((void**)&qkv_p, g_qkv);
    cudaGetSymbolAddress((void**)&o_p,   g_o);
    cudaGetSymbolAddress((void**)&x1_p,  g_x1);
    cudaGetSymbolAddress((void**)&ff_p,  g_ff);

    // 1) LN1
    ln_kernel<<<MM, 256>>>(x, ln1_g, ln1_b, h_p);
    // 2) QKV projection: [4096,3072] = h @ in_proj_w^T
    gemm_kernel<0><<<dim3(3 * DD / 128, MM / 128), 256>>>(h_p, in_proj_w, in_proj_b, nullptr, qkv_p, MM, 3 * DD, DD);
    // 3) banded attention
    attn_kernel<<<dim3(TT / 64, BB * NH), 64>>>(qkv_p, o_p);
    // 4) out projection + residual(x)
    gemm_kernel<1><<<dim3(DD / 128, MM / 128), 256>>>(o_p, out_w, out_b, x, x1_p, MM, DD, DD);
    // 5) LN2
    ln_kernel<<<MM, 256>>>(x1_p, ln2_g, ln2_b, h_p);
    // 6) FFN up + exact GELU
    gemm_kernel<2><<<dim3(4 * DD / 128, MM / 128), 256>>>(h_p, w1, b1, nullptr, ff_p, MM, 4 * DD, DD);
    // 7) FFN down + residual(x1) -> out
    gemm_kernel<1><<<dim3(DD / 128, MM / 128), 256>>>(ff_p, w2, b2, x1_p, out, MM, DD, 4 * DD);
}

// round 16
// speedup vs baseline: 1.0077x; 1.0077x over previous
#include <cuda_runtime.h>
#include <cuda_bf16.h>
#include <cstdint>

// ---------------- problem constants ----------------
#define BB 2
#define TT 2048
#define DD 1024
#define NH 16
#define HDIM 64
#define WIN 10
#define MM (BB*TT)          // 4096 rows

// ---------------- scratch (static device, allocation-free) ----------------
__device__ float g_h[(size_t)MM * DD];        // LN output (reused)
__device__ float g_qkv[(size_t)MM * 3 * DD];  // qkv
__device__ float g_o[(size_t)MM * DD];        // attention output
__device__ float g_x1[(size_t)MM * DD];       // x + attn_out
__device__ float g_ff[(size_t)MM * 4 * DD];   // FFN hidden

// packed f32x2 helpers
#define FFMA_X2(d, a, b) asm("fma.rn.f32x2 %0, %1, %2, %0;" : "+l"(d) : "l"(a), "l"(b))
__device__ __forceinline__ unsigned long long pack_dup(float x) {
    unsigned long long r;
    unsigned u = __float_as_uint(x);
    asm("mov.b64 %0, {%1, %1};" : "=l"(r) : "r"(u));
    return r;
}
__device__ __forceinline__ void unpack_x2(unsigned long long v, float& lo, float& hi) {
    asm("mov.b64 {%0, %1}, %2;" : "=f"(lo), "=f"(hi) : "l"(v));
}

// ---------------- LayerNorm ----------------
__global__ void ln_kernel(const float* __restrict__ x, const float* __restrict__ g,
                          const float* __restrict__ b, float* __restrict__ out) {
    int row = blockIdx.x;
    const float* xp = x + (size_t)row * DD;
    int t = threadIdx.x; // 256 threads, 4 elements each
    float4 v = *(const float4*)(xp + t * 4);
    float s  = v.x + v.y + v.z + v.w;
    float ss = v.x*v.x + v.y*v.y + v.z*v.z + v.w*v.w;
    __shared__ float rs[8], rss[8];
    #pragma unroll
    for (int off = 16; off; off >>= 1) {
        s  += __shfl_xor_sync(0xffffffffu, s,  off);
        ss += __shfl_xor_sync(0xffffffffu, ss, off);
    }
    if ((t & 31) == 0) { rs[t >> 5] = s; rss[t >> 5] = ss; }
    __syncthreads();
    __shared__ float mean_sh, rstd_sh;
    if (t == 0) {
        float S = 0.f, SS = 0.f;
        #pragma unroll
        for (int i = 0; i < 8; i++) { S += rs[i]; SS += rss[i]; }
        float mean = S * (1.0f / DD);
        float var  = SS * (1.0f / DD) - mean * mean;
        mean_sh = mean;
        rstd_sh = rsqrtf(var + 1e-5f);
    }
    __syncthreads();
    float mean = mean_sh, rstd = rstd_sh;
    float4 gv = *(const float4*)(g + t * 4);
    float4 bv = *(const float4*)(b + t * 4);
    float4 ov;
    ov.x = (v.x - mean) * rstd * gv.x + bv.x;
    ov.y = (v.y - mean) * rstd * gv.y + bv.y;
    ov.z = (v.z - mean) * rstd * gv.z + bv.z;
    ov.w = (v.w - mean) * rstd * gv.w + bv.w;
    *(float4*)(out + (size_t)row * DD + t * 4) = ov;
}

// ---------------- GEMM: C[M,N] = A[M,K] @ W[N,K]^T + bias (+epilogue) ----------------
// Double-buffered smem, global->register prefetch, packed f32x2 FMA inner loop.
// EPI: 0 = none, 1 = += R (residual), 2 = exact GELU
template<int EPI>
__global__ void __launch_bounds__(256)
gemm_kernel(const float* __restrict__ A, const float* __restrict__ W,
            const float* __restrict__ bias, const float* __restrict__ R,
            float* __restrict__ C, int M, int N, int K) {
    constexpr int BM = 128, BN = 128, BK = 16;
    __shared__ float As[2][BK][BM];
    __shared__ float Bs[2][BK][BN];
    int tid = threadIdx.x;                 // 256
    int tx = tid & 15, ty = tid >> 4;      // 16x16 thread grid, 8x8 micro-tile
    int bm = blockIdx.y * BM, bn = blockIdx.x * BN;

    // each thread stages 2 float4 of A and 2 of B per tile
    int r0 = tid >> 2, c40 = (tid & 3) * 4;                 // pos = tid
    int r1 = (256 + tid) >> 2, c41 = ((256 + tid) & 3) * 4; // pos = 256+tid

    // accumulators: 8 rows x 4 packed col-pairs (covers 8 cols)
    unsigned long long acc[8][4];
    #pragma unroll
    for (int i = 0; i < 8; i++)
        #pragma unroll
        for (int j = 0; j < 4; j++) acc[i][j] = 0ull;

    // prologue: load tile 0 into buffer 0
    float4 a0 = *(const float4*)&A[(size_t)(bm + r0) * K + c40];
    float4 a1 = *(const float4*)&A[(size_t)(bm + r1) * K + c41];
    float4 b0 = *(const float4*)&W[(size_t)(bn + r0) * K + c40];
    float4 b1 = *(const float4*)&W[(size_t)(bn + r1) * K + c41];
    As[0][c40 + 0][r0] = a0.x; As[0][c40 + 1][r0] = a0.y; As[0][c40 + 2][r0] = a0.z; As[0][c40 + 3][r0] = a0.w;
    As[0][c41 + 0][r1] = a1.x; As[0][c41 + 1][r1] = a1.y; As[0][c41 + 2][r1] = a1.z; As[0][c41 + 3][r1] = a1.w;
    Bs[0][c40 + 0][r0] = b0.x; Bs[0][c40 + 1][r0] = b0.y; Bs[0][c40 + 2][r0] = b0.z; Bs[0][c40 + 3][r0] = b0.w;
    Bs[0][c41 + 0][r1] = b1.x; Bs[0][c41 + 1][r1] = b1.y; Bs[0][c41 + 2][r1] = b1.z; Bs[0][c41 + 3][r1] = b1.w;
    __syncthreads();

    int nk = K / BK;
    int cur = 0;
    for (int kt = 0; kt < nk; kt++) {
        // prefetch next tile into registers (overlaps with FMA block below)
        bool has_next = (kt + 1) < nk;
        if (has_next) {
            int k0 = (kt + 1) * BK;
            a0 = *(const float4*)&A[(size_t)(bm + r0) * K + k0 + c40];
            a1 = *(const float4*)&A[(size_t)(bm + r1) * K + k0 + c41];
            b0 = *(const float4*)&W[(size_t)(bn + r0) * K + k0 + c40];
            b1 = *(const float4*)&W[(size_t)(bn + r1) * K + k0 + c41];
        }
        // compute from current buffer: packed f32x2 FMAs
        #pragma unroll
        for (int k = 0; k < BK; k++) {
            float a[8];
            *(float4*)&a[0] = *(const float4*)&As[cur][k][ty * 8];
            *(float4*)&a[4] = *(const float4*)&As[cur][k][ty * 8 + 4];
            ulonglong2 t0 = *(const ulonglong2*)&Bs[cur][k][tx * 8];      // col pairs 0,1
            ulonglong2 t1 = *(const ulonglong2*)&Bs[cur][k][tx * 8 + 4];  // col pairs 2,3
            unsigned long long bp[4] = {t0.x, t0.y, t1.x, t1.y};
            #pragma unroll
            for (int i = 0; i < 8; i++) {
                unsigned long long a2 = pack_dup(a[i]);
                #pragma unroll
                for (int j = 0; j < 4; j++)
                    FFMA_X2(acc[i][j], a2, bp[j]);
            }
        }
        // store prefetched tile into the other buffer, single barrier
        if (has_next) {
            int nxt = cur ^ 1;
            As[nxt][c40 + 0][r0] = a0.x; As[nxt][c40 + 1][r0] = a0.y; As[nxt][c40 + 2][r0] = a0.z; As[nxt][c40 + 3][r0] = a0.w;
            As[nxt][c41 + 0][r1] = a1.x; As[nxt][c41 + 1][r1] = a1.y; As[nxt][c41 + 2][r1] = a1.z; As[nxt][c41 + 3][r1] = a1.w;
            Bs[nxt][c40 + 0][r0] = b0.x; Bs[nxt][c40 + 1][r0] = b0.y; Bs[nxt][c40 + 2][r0] = b0.z; Bs[nxt][c40 + 3][r0] = b0.w;
            Bs[nxt][c41 + 0][r1] = b1.x; Bs[nxt][c41 + 1][r1] = b1.y; Bs[nxt][c41 + 2][r1] = b1.z; Bs[nxt][c41 + 3][r1] = b1.w;
            __syncthreads();
            cur = nxt;
        }
    }

    // epilogue
    #pragma unroll
    for (int i = 0; i < 8; i++) {
        int row = bm + ty * 8 + i;
        #pragma unroll
        for (int j = 0; j < 4; j++) {
            float lo, hi;
            unpack_x2(acc[i][j], lo, hi);
            int col = bn + tx * 8 + j * 2;
            float v0 = lo + bias[col];
            float v1 = hi + bias[col + 1];
            if (EPI == 1) {
                v0 += R[(size_t)row * N + col];
                v1 += R[(size_t)row * N + col + 1];
            }
            if (EPI == 2) {
                v0 = 0.5f * v0 * (1.0f + erff(v0 * 0.70710678118654752f));
                v1 = 0.5f * v1 * (1.0f + erff(v1 * 0.70710678118654752f));
            }
            C[(size_t)row * N + col]     = v0;
            C[(size_t)row * N + col + 1] = v1;
        }
    }
}

// ---------------- banded-causal flash attention ----------------
// grid: (T/64 query tiles, B*H). block: 64 threads, one query row each.
__global__ void __launch_bounds__(64)
attn_kernel(const float* __restrict__ qkv, float* __restrict__ o_out) {
    __shared__ float Ks[64][HDIM];
    __shared__ float Vs[64][HDIM];
    __shared__ float Ss[64][65];
    int bh = blockIdx.y;
    int b = bh / NH, h = bh % NH;
    int q0 = blockIdx.x * 64;
    int t = threadIdx.x;          // 0..63
    int qi = q0 + t;
    const int rowstride = 3 * DD;
    const float* qptr = qkv + ((size_t)(b * TT + qi)) * rowstride + h * HDIM;
    float q[HDIM], o[HDIM];
    #pragma unroll
    for (int d = 0; d < HDIM; d += 4) {
        float4 v4 = *(const float4*)(qptr + d);
        q[d] = v4.x; q[d+1] = v4.y; q[d+2] = v4.z; q[d+3] = v4.w;
    }
    #pragma unroll
    for (int d = 0; d < HDIM; d++) o[d] = 0.f;
    float m = -1e30f, l = 0.f;
    const float scale = 0.125f;   // 1/sqrt(64)

    int kmax = q0 + 63 + WIN;
    if (kmax > TT - 1) kmax = TT - 1;
    int nkt = kmax / 64 + 1;

    for (int kt = 0; kt < nkt; kt++) {
        int kbase = kt * 64;
        // stage K,V (thread t loads key row kbase+t)
        {
            int kj = kbase + t;
            if (kj < TT) {
                const float* kptr = qkv + ((size_t)(b * TT + kj)) * rowstride + DD + h * HDIM;
                const float* vptr = kptr + DD;
                #pragma unroll
                for (int d = 0; d < HDIM; d += 4) {
                    *(float4*)&Ks[t][d] = *(const float4*)(kptr + d);
                    *(float4*)&Vs[t][d] = *(const float4*)(vptr + d);
                }
            } else {
                #pragma unroll
                for (int d = 0; d < HDIM; d += 4) {
                    *(float4*)&Ks[t][d] = make_float4(0.f, 0.f, 0.f, 0.f);
                    *(float4*)&Vs[t][d] = make_float4(0.f, 0.f, 0.f, 0.f);
                }
            }
        }
        __syncthreads();

        int jmax = qi + WIN - kbase;         // band limit
        if (jmax > 63) jmax = 63;
        int jT = TT - 1 - kbase;             // sequence limit
        if (jmax > jT) jmax = jT;

        if (jmax >= 0) {
            float tmax = -1e30f;
            for (int j = 0; j <= jmax; j++) {
                float s = 0.f;
                #pragma unroll
                for (int d = 0; d < HDIM; d++) s += q[d] * Ks[j][d];
                s *= scale;
                Ss[t][j] = s;
                tmax = fmaxf(tmax, s);
            }
            float mnew = fmaxf(m, tmax);
            float corr = __expf(m - mnew);
            l *= corr;
            #pragma unroll
            for (int d = 0; d < HDIM; d++) o[d] *= corr;
            for (int j = 0; j <= jmax; j++) {
                float p = __expf(Ss[t][j] - mnew);
                l += p;
                #pragma unroll
                for (int d = 0; d < HDIM; d++) o[d] += p * Vs[j][d];
            }
            m = mnew;
        }
        __syncthreads();
    }
    float inv = 1.0f / l;
    float* optr = o_out + ((size_t)(b * TT + qi)) * DD + h * HDIM;
    #pragma unroll
    for (int d = 0; d < HDIM; d += 4) {
        float4 v4 = make_float4(o[d] * inv, o[d+1] * inv, o[d+2] * inv, o[d+3] * inv);
        *(float4*)(optr + d) = v4;
    }
}

// ---------------- launch ----------------
extern "C" void kernel_launch(void* const* d_in, const int* in_sizes, int n_in,
                              void* d_out, int out_size) {
    const float* x         = (const float*)d_in[0];
    const float* in_proj_w = (const float*)d_in[1];
    const float* in_proj_b = (const float*)d_in[2];
    const float* out_w     = (const float*)d_in[3];
    const float* out_b     = (const float*)d_in[4];
    const float* ln1_g     = (const float*)d_in[5];
    const float* ln1_b     = (const float*)d_in[6];
    const float* w1        = (const float*)d_in[7];
    const float* b1        = (const float*)d_in[8];
    const float* w2        = (const float*)d_in[9];
    const float* b2        = (const float*)d_in[10];
    const float* ln2_g     = (const float*)d_in[11];
    const float* ln2_b     = (const float*)d_in[12];
    float* out = (float*)d_out;

    float *h_p, *qkv_p, *o_p, *x1_p, *ff_p;
    cudaGetSymbolAddress((void**)&h_p,   g_h);
    cudaGetSymbolAddress((void**)&qkv_p, g_qkv);
    cudaGetSymbolAddress((void**)&o_p,   g_o);
    cudaGetSymbolAddress((void**)&x1_p,  g_x1);
    cudaGetSymbolAddress((void**)&ff_p,  g_ff);

    // 1) LN1
    ln_kernel<<<MM, 256>>>(x, ln1_g, ln1_b, h_p);
    // 2) QKV projection: [4096,3072] = h @ in_proj_w^T
    gemm_kernel<0><<<dim3(3 * DD / 128, MM / 128), 256>>>(h_p, in_proj_w, in_proj_b, nullptr, qkv_p, MM, 3 * DD, DD);
    // 3) banded attention
    attn_kernel<<<dim3(TT / 64, BB * NH), 64>>>(qkv_p, o_p);
    // 4) out projection + residual(x)
    gemm_kernel<1><<<dim3(DD / 128, MM / 128), 256>>>(o_p, out_w, out_b, x, x1_p, MM, DD, DD);
    // 5) LN2
    ln_kernel<<<MM, 256>>>(x1_p, ln2_g, ln2_b, h_p);
    // 6) FFN up + exact GELU
    gemm_kernel<2><<<dim3(4 * DD / 128, MM / 128), 256>>>(h_p, w1, b1, nullptr, ff_p, MM, 4 * DD, DD);
    // 7) FFN down + residual(x1) -> out
    gemm_kernel<1><<<dim3(DD / 128, MM / 128), 256>>>(ff_p, w2, b2, x1_p, out, MM, DD, 4 * DD);
}

// round 17
// speedup vs baseline: 1.0445x; 1.0365x over previous
#include <cuda_runtime.h>
#include <cuda_bf16.h>
#include <cstdint>

// ---------------- problem constants ----------------
#define BB 2
#define TT 2048
#define DD 1024
#define NH 16
#define HDIM 64
#define WIN 10
#define MM (BB*TT)          // 4096 rows

// ---------------- scratch (static device, allocation-free) ----------------
__device__ float g_h[(size_t)MM * DD];        // LN output (reused)
__device__ float g_qkv[(size_t)MM * 3 * DD];  // qkv
__device__ float g_o[(size_t)MM * DD];        // attention output
__device__ float g_x1[(size_t)MM * DD];       // x + attn_out
__device__ float g_ff[(size_t)MM * 4 * DD];   // FFN hidden

// packed f32x2 helpers
#define FFMA_X2(d, a, b) asm("fma.rn.f32x2 %0, %1, %2, %0;" : "+l"(d) : "l"(a), "l"(b))
__device__ __forceinline__ unsigned long long pack_dup(float x) {
    unsigned long long r;
    unsigned u = __float_as_uint(x);
    asm("mov.b64 %0, {%1, %1};" : "=l"(r) : "r"(u));
    return r;
}
__device__ __forceinline__ void unpack_x2(unsigned long long v, float& lo, float& hi) {
    asm("mov.b64 {%0, %1}, %2;" : "=f"(lo), "=f"(hi) : "l"(v));
}

// ---------------- LayerNorm ----------------
__global__ void ln_kernel(const float* __restrict__ x, const float* __restrict__ g,
                          const float* __restrict__ b, float* __restrict__ out) {
    int row = blockIdx.x;
    const float* xp = x + (size_t)row * DD;
    int t = threadIdx.x; // 256 threads, 4 elements each
    float4 v = *(const float4*)(xp + t * 4);
    float s  = v.x + v.y + v.z + v.w;
    float ss = v.x*v.x + v.y*v.y + v.z*v.z + v.w*v.w;
    __shared__ float rs[8], rss[8];
    #pragma unroll
    for (int off = 16; off; off >>= 1) {
        s  += __shfl_xor_sync(0xffffffffu, s,  off);
        ss += __shfl_xor_sync(0xffffffffu, ss, off);
    }
    if ((t & 31) == 0) { rs[t >> 5] = s; rss[t >> 5] = ss; }
    __syncthreads();
    __shared__ float mean_sh, rstd_sh;
    if (t == 0) {
        float S = 0.f, SS = 0.f;
        #pragma unroll
        for (int i = 0; i < 8; i++) { S += rs[i]; SS += rss[i]; }
        float mean = S * (1.0f / DD);
        float var  = SS * (1.0f / DD) - mean * mean;
        mean_sh = mean;
        rstd_sh = rsqrtf(var + 1e-5f);
    }
    __syncthreads();
    float mean = mean_sh, rstd = rstd_sh;
    float4 gv = *(const float4*)(g + t * 4);
    float4 bv = *(const float4*)(b + t * 4);
    float4 ov;
    ov.x = (v.x - mean) * rstd * gv.x + bv.x;
    ov.y = (v.y - mean) * rstd * gv.y + bv.y;
    ov.z = (v.z - mean) * rstd * gv.z + bv.z;
    ov.w = (v.w - mean) * rstd * gv.w + bv.w;
    *(float4*)(out + (size_t)row * DD + t * 4) = ov;
}

// ---------------- GEMM: C[M,N] = A[M,K] @ W[N,K]^T + bias (+epilogue) ----------------
// Double-buffered smem, global->register prefetch, packed f32x2 FMA inner loop.
// __launch_bounds__(256, 2): cap regs at 128 so 2 CTAs fit per SM (occupancy fix).
// EPI: 0 = none, 1 = += R (residual), 2 = exact GELU
template<int EPI>
__global__ void __launch_bounds__(256, 2)
gemm_kernel(const float* __restrict__ A, const float* __restrict__ W,
            const float* __restrict__ bias, const float* __restrict__ R,
            float* __restrict__ C, int M, int N, int K) {
    constexpr int BM = 128, BN = 128, BK = 16;
    __shared__ float As[2][BK][BM];
    __shared__ float Bs[2][BK][BN];
    int tid = threadIdx.x;                 // 256
    int tx = tid & 15, ty = tid >> 4;      // 16x16 thread grid, 8x8 micro-tile
    int bm = blockIdx.y * BM, bn = blockIdx.x * BN;

    // each thread stages 2 float4 of A and 2 of B per tile
    int r0 = tid >> 2, c40 = (tid & 3) * 4;                 // pos = tid
    int r1 = (256 + tid) >> 2, c41 = ((256 + tid) & 3) * 4; // pos = 256+tid

    // accumulators: 8 rows x 4 packed col-pairs (covers 8 cols)
    unsigned long long acc[8][4];
    #pragma unroll
    for (int i = 0; i < 8; i++)
        #pragma unroll
        for (int j = 0; j < 4; j++) acc[i][j] = 0ull;

    // prologue: load tile 0 into buffer 0
    float4 a0 = *(const float4*)&A[(size_t)(bm + r0) * K + c40];
    float4 a1 = *(const float4*)&A[(size_t)(bm + r1) * K + c41];
    float4 b0 = *(const float4*)&W[(size_t)(bn + r0) * K + c40];
    float4 b1 = *(const float4*)&W[(size_t)(bn + r1) * K + c41];
    As[0][c40 + 0][r0] = a0.x; As[0][c40 + 1][r0] = a0.y; As[0][c40 + 2][r0] = a0.z; As[0][c40 + 3][r0] = a0.w;
    As[0][c41 + 0][r1] = a1.x; As[0][c41 + 1][r1] = a1.y; As[0][c41 + 2][r1] = a1.z; As[0][c41 + 3][r1] = a1.w;
    Bs[0][c40 + 0][r0] = b0.x; Bs[0][c40 + 1][r0] = b0.y; Bs[0][c40 + 2][r0] = b0.z; Bs[0][c40 + 3][r0] = b0.w;
    Bs[0][c41 + 0][r1] = b1.x; Bs[0][c41 + 1][r1] = b1.y; Bs[0][c41 + 2][r1] = b1.z; Bs[0][c41 + 3][r1] = b1.w;
    __syncthreads();

    int nk = K / BK;
    int cur = 0;
    for (int kt = 0; kt < nk; kt++) {
        // prefetch next tile into registers (overlaps with FMA block below)
        bool has_next = (kt + 1) < nk;
        if (has_next) {
            int k0 = (kt + 1) * BK;
            a0 = *(const float4*)&A[(size_t)(bm + r0) * K + k0 + c40];
            a1 = *(const float4*)&A[(size_t)(bm + r1) * K + k0 + c41];
            b0 = *(const float4*)&W[(size_t)(bn + r0) * K + k0 + c40];
            b1 = *(const float4*)&W[(size_t)(bn + r1) * K + k0 + c41];
        }
        // compute from current buffer: packed f32x2 FMAs
        #pragma unroll
        for (int k = 0; k < BK; k++) {
            float a[8];
            *(float4*)&a[0] = *(const float4*)&As[cur][k][ty * 8];
            *(float4*)&a[4] = *(const float4*)&As[cur][k][ty * 8 + 4];
            ulonglong2 t0 = *(const ulonglong2*)&Bs[cur][k][tx * 8];      // col pairs 0,1
            ulonglong2 t1 = *(const ulonglong2*)&Bs[cur][k][tx * 8 + 4];  // col pairs 2,3
            unsigned long long bp[4] = {t0.x, t0.y, t1.x, t1.y};
            #pragma unroll
            for (int i = 0; i < 8; i++) {
                unsigned long long a2 = pack_dup(a[i]);
                #pragma unroll
                for (int j = 0; j < 4; j++)
                    FFMA_X2(acc[i][j], a2, bp[j]);
            }
        }
        // store prefetched tile into the other buffer, single barrier
        if (has_next) {
            int nxt = cur ^ 1;
            As[nxt][c40 + 0][r0] = a0.x; As[nxt][c40 + 1][r0] = a0.y; As[nxt][c40 + 2][r0] = a0.z; As[nxt][c40 + 3][r0] = a0.w;
            As[nxt][c41 + 0][r1] = a1.x; As[nxt][c41 + 1][r1] = a1.y; As[nxt][c41 + 2][r1] = a1.z; As[nxt][c41 + 3][r1] = a1.w;
            Bs[nxt][c40 + 0][r0] = b0.x; Bs[nxt][c40 + 1][r0] = b0.y; Bs[nxt][c40 + 2][r0] = b0.z; Bs[nxt][c40 + 3][r0] = b0.w;
            Bs[nxt][c41 + 0][r1] = b1.x; Bs[nxt][c41 + 1][r1] = b1.y; Bs[nxt][c41 + 2][r1] = b1.z; Bs[nxt][c41 + 3][r1] = b1.w;
            __syncthreads();
            cur = nxt;
        }
    }

    // epilogue
    #pragma unroll
    for (int i = 0; i < 8; i++) {
        int row = bm + ty * 8 + i;
        #pragma unroll
        for (int j = 0; j < 4; j++) {
            float lo, hi;
            unpack_x2(acc[i][j], lo, hi);
            int col = bn + tx * 8 + j * 2;
            float v0 = lo + bias[col];
            float v1 = hi + bias[col + 1];
            if (EPI == 1) {
                v0 += R[(size_t)row * N + col];
                v1 += R[(size_t)row * N + col + 1];
            }
            if (EPI == 2) {
                v0 = 0.5f * v0 * (1.0f + erff(v0 * 0.70710678118654752f));
                v1 = 0.5f * v1 * (1.0f + erff(v1 * 0.70710678118654752f));
            }
            C[(size_t)row * N + col]     = v0;
            C[(size_t)row * N + col + 1] = v1;
        }
    }
}

// ---------------- banded-causal flash attention ----------------
// grid: (T/64 query tiles, B*H). block: 64 threads, one query row each.
__global__ void __launch_bounds__(64)
attn_kernel(const float* __restrict__ qkv, float* __restrict__ o_out) {
    __shared__ float Ks[64][HDIM];
    __shared__ float Vs[64][HDIM];
    __shared__ float Ss[64][65];
    int bh = blockIdx.y;
    int b = bh / NH, h = bh % NH;
    int q0 = blockIdx.x * 64;
    int t = threadIdx.x;          // 0..63
    int qi = q0 + t;
    const int rowstride = 3 * DD;
    const float* qptr = qkv + ((size_t)(b * TT + qi)) * rowstride + h * HDIM;
    float q[HDIM], o[HDIM];
    #pragma unroll
    for (int d = 0; d < HDIM; d += 4) {
        float4 v4 = *(const float4*)(qptr + d);
        q[d] = v4.x; q[d+1] = v4.y; q[d+2] = v4.z; q[d+3] = v4.w;
    }
    #pragma unroll
    for (int d = 0; d < HDIM; d++) o[d] = 0.f;
    float m = -1e30f, l = 0.f;
    const float scale = 0.125f;   // 1/sqrt(64)

    int kmax = q0 + 63 + WIN;
    if (kmax > TT - 1) kmax = TT - 1;
    int nkt = kmax / 64 + 1;

    for (int kt = 0; kt < nkt; kt++) {
        int kbase = kt * 64;
        // stage K,V (thread t loads key row kbase+t)
        {
            int kj = kbase + t;
            if (kj < TT) {
                const float* kptr = qkv + ((size_t)(b * TT + kj)) * rowstride + DD + h * HDIM;
                const float* vptr = kptr + DD;
                #pragma unroll
                for (int d = 0; d < HDIM; d += 4) {
                    *(float4*)&Ks[t][d] = *(const float4*)(kptr + d);
                    *(float4*)&Vs[t][d] = *(const float4*)(vptr + d);
                }
            } else {
                #pragma unroll
                for (int d = 0; d < HDIM; d += 4) {
                    *(float4*)&Ks[t][d] = make_float4(0.f, 0.f, 0.f, 0.f);
                    *(float4*)&Vs[t][d] = make_float4(0.f, 0.f, 0.f, 0.f);
                }
            }
        }
        __syncthreads();

        int jmax = qi + WIN - kbase;         // band limit
        if (jmax > 63) jmax = 63;
        int jT = TT - 1 - kbase;             // sequence limit
        if (jmax > jT) jmax = jT;

        if (jmax >= 0) {
            float tmax = -1e30f;
            for (int j = 0; j <= jmax; j++) {
                float s = 0.f;
                #pragma unroll
                for (int d = 0; d < HDIM; d++) s += q[d] * Ks[j][d];
                s *= scale;
                Ss[t][j] = s;
                tmax = fmaxf(tmax, s);
            }
            float mnew = fmaxf(m, tmax);
            float corr = __expf(m - mnew);
            l *= corr;
            #pragma unroll
            for (int d = 0; d < HDIM; d++) o[d] *= corr;
            for (int j = 0; j <= jmax; j++) {
                float p = __expf(Ss[t][j] - mnew);
                l += p;
                #pragma unroll
                for (int d = 0; d < HDIM; d++) o[d] += p * Vs[j][d];
            }
            m = mnew;
        }
        __syncthreads();
    }
    float inv = 1.0f / l;
    float* optr = o_out + ((size_t)(b * TT + qi)) * DD + h * HDIM;
    #pragma unroll
    for (int d = 0; d < HDIM; d += 4) {
        float4 v4 = make_float4(o[d] * inv, o[d+1] * inv, o[d+2] * inv, o[d+3] * inv);
        *(float4*)(optr + d) = v4;
    }
}

// ---------------- launch ----------------
extern "C" void kernel_launch(void* const* d_in, const int* in_sizes, int n_in,
                              void* d_out, int out_size) {
    const float* x         = (const float*)d_in[0];
    const float* in_proj_w = (const float*)d_in[1];
    const float* in_proj_b = (const float*)d_in[2];
    const float* out_w     = (const float*)d_in[3];
    const float* out_b     = (const float*)d_in[4];
    const float* ln1_g     = (const float*)d_in[5];
    const float* ln1_b     = (const float*)d_in[6];
    const float* w1        = (const float*)d_in[7];
    const float* b1        = (const float*)d_in[8];
    const float* w2        = (const float*)d_in[9];
    const float* b2        = (const float*)d_in[10];
    const float* ln2_g     = (const float*)d_in[11];
    const float* ln2_b     = (const float*)d_in[12];
    float* out = (float*)d_out;

    float *h_p, *qkv_p, *o_p, *x1_p, *ff_p;
    cudaGetSymbolAddress((void**)&h_p,   g_h);
    cudaGetSymbolAddress((void**)&qkv_p, g_qkv);
    cudaGetSymbolAddress((void**)&o_p,   g_o);
    cudaGetSymbolAddress((void**)&x1_p,  g_x1);
    cudaGetSymbolAddress((void**)&ff_p,  g_ff);

    // 1) LN1
    ln_kernel<<<MM, 256>>>(x, ln1_g, ln1_b, h_p);
    // 2) QKV projection: [4096,3072] = h @ in_proj_w^T
    gemm_kernel<0><<<dim3(3 * DD / 128, MM / 128), 256>>>(h_p, in_proj_w, in_proj_b, nullptr, qkv_p, MM, 3 * DD, DD);
    // 3) banded attention
    attn_kernel<<<dim3(TT / 64, BB * NH), 64>>>(qkv_p, o_p);
    // 4) out projection + residual(x)
    gemm_kernel<1><<<dim3(DD / 128, MM / 128), 256>>>(o_p, out_w, out_b, x, x1_p, MM, DD, DD);
    // 5) LN2
    ln_kernel<<<MM, 256>>>(x1_p, ln2_g, ln2_b, h_p);
    // 6) FFN up + exact GELU
    gemm_kernel<2><<<dim3(4 * DD / 128, MM / 128), 256>>>(h_p, w1, b1, nullptr, ff_p, MM, 4 * DD, DD);
    // 7) FFN down + residual(x1) -> out
    gemm_kernel<1><<<dim3(DD / 128, MM / 128), 256>>>(ff_p, w2, b2, x1_p, out, MM, DD, 4 * DD);
}